// round 2
// baseline (speedup 1.0000x reference)
#include <cuda_runtime.h>
#include <cuda_bf16.h>
#include <math.h>

#define N_LEVELS 16
#define TBL (1u << 19)
#define BLOCK 128

struct Meta {
    float scale[N_LEVELS];
    int   res[N_LEVELS];
    unsigned hashed_mask;
};

__device__ __forceinline__ float softplus10(float v) {
    float t = 10.0f * v;
    float e = __expf(-fabsf(t));
    return (log1pf(e) + fmaxf(t, 0.0f)) * 0.1f;
}

__device__ __forceinline__ unsigned long long pack2(float a) {
    unsigned long long r;
    asm("mov.b64 %0, {%1, %1};" : "=l"(r) : "r"(__float_as_uint(a)));
    return r;
}

__device__ __forceinline__ void fma2(unsigned long long& acc,
                                     unsigned long long w,
                                     unsigned long long a) {
    asm("fma.rn.f32x2 %0, %1, %2, %0;" : "+l"(acc) : "l"(w), "l"(a));
}

// acc2[32] packed pairs: acc2[k] holds outputs (2k, 2k+1).
// wt is input-major: wt[i*64 + j].
template <int NIN>
__device__ __forceinline__ void layer_accum(const float* __restrict__ wt,
                                            const float* __restrict__ act,
                                            int tid, unsigned long long* acc2) {
#pragma unroll
    for (int k = 0; k < 32; k++) acc2[k] = 0ull;
    for (int i = 0; i < NIN; i++) {
        unsigned long long a2 = pack2(act[i * BLOCK + tid]);
        const ulonglong2* wr = (const ulonglong2*)(wt + i * 64);
#pragma unroll
        for (int q = 0; q < 16; q++) {
            ulonglong2 w = wr[q];
            fma2(acc2[2 * q + 0], w.x, a2);
            fma2(acc2[2 * q + 1], w.y, a2);
        }
    }
}

__device__ __forceinline__ void unpack2(unsigned long long v, float& lo, float& hi) {
    unsigned ulo, uhi;
    asm("mov.b64 {%0, %1}, %2;" : "=r"(ulo), "=r"(uhi) : "l"(v));
    lo = __uint_as_float(ulo);
    hi = __uint_as_float(uhi);
}

__global__ void __launch_bounds__(BLOCK)
sdf_kernel(const float* __restrict__ x,
           const float* __restrict__ grid,
           const float* __restrict__ W1,
           const float* __restrict__ W2,
           const float* __restrict__ W3,
           const float* __restrict__ W4,
           float* __restrict__ out,
           int N, Meta meta)
{
    extern __shared__ float sm[];
    float* wt1 = sm;                 // [32][64] transposed W1
    float* wt2 = wt1 + 32 * 64;      // [64][64] transposed W2
    float* wt3 = wt2 + 64 * 64;      // [64][64] transposed W3
    float* w4s = wt3 + 64 * 64;      // [64]
    float* act = w4s + 64;           // [64][BLOCK] per-thread activation columns

    const int tid = threadIdx.x;

    // Cooperative weight load with transpose (input-major rows of 64 floats)
    for (int idx = tid; idx < 64 * 32; idx += BLOCK) {
        int j = idx >> 5, i = idx & 31;          // W1[j][i]
        wt1[i * 64 + j] = W1[idx];
    }
    for (int idx = tid; idx < 64 * 64; idx += BLOCK) {
        int j = idx >> 6, i = idx & 63;
        wt2[i * 64 + j] = W2[idx];
        wt3[i * 64 + j] = W3[idx];
    }
    if (tid < 64) w4s[tid] = W4[tid];
    __syncthreads();

    const int p = blockIdx.x * BLOCK + tid;
    if (p >= N) return;

    const float px = x[p * 3 + 0];
    const float py = x[p * 3 + 1];
    const float pz = x[p * 3 + 2];

    // ---- Hash-grid encoding: 16 levels x 2 features -> act rows 0..31 ----
    for (int l = 0; l < N_LEVELS; l++) {
        const float s = meta.scale[l];
        const int res = meta.res[l];
        const bool hashed = (meta.hashed_mask >> l) & 1u;

        float fx = fmaf(px, s, 0.5f);
        float fy = fmaf(py, s, 0.5f);
        float fz = fmaf(pz, s, 0.5f);
        float fx0 = floorf(fx), fy0 = floorf(fy), fz0 = floorf(fz);
        float rx = fx - fx0, ry = fy - fy0, rz = fz - fz0;
        int ix = (int)fx0, iy = (int)fy0, iz = (int)fz0;

        const float2* g = (const float2*)grid + (size_t)l * TBL;
        float a0 = 0.0f, a1 = 0.0f;

#pragma unroll
        for (int c = 0; c < 8; c++) {
            const int cx = c & 1, cy = (c >> 1) & 1, cz = (c >> 2) & 1;
            float w = (cx ? rx : 1.0f - rx) *
                      (cy ? ry : 1.0f - ry) *
                      (cz ? rz : 1.0f - rz);
            unsigned idx;
            if (hashed) {
                unsigned gx = (unsigned)(ix + cx);
                unsigned gy = (unsigned)(iy + cy);
                unsigned gz = (unsigned)(iz + cz);
                idx = (gx * 1u) ^ (gy * 2654435761u) ^ (gz * 805459861u);
                idx &= (TBL - 1u);
            } else {
                int gx = min(max(ix + cx, 0), res - 1);
                int gy = min(max(iy + cy, 0), res - 1);
                int gz = min(max(iz + cz, 0), res - 1);
                idx = (unsigned)(gx + res * (gy + res * gz));
            }
            float2 f = __ldg(&g[idx]);
            a0 = fmaf(w, f.x, a0);
            a1 = fmaf(w, f.y, a1);
        }
        act[(2 * l + 0) * BLOCK + tid] = a0;
        act[(2 * l + 1) * BLOCK + tid] = a1;
    }

    // ---- MLP (packed f32x2 math) ----
    unsigned long long acc2[32];
    float lo, hi;

    layer_accum<32>(wt1, act, tid, acc2);
#pragma unroll
    for (int k = 0; k < 32; k++) {
        unpack2(acc2[k], lo, hi);
        act[(2 * k + 0) * BLOCK + tid] = softplus10(lo);
        act[(2 * k + 1) * BLOCK + tid] = softplus10(hi);
    }

    layer_accum<64>(wt2, act, tid, acc2);
#pragma unroll
    for (int k = 0; k < 32; k++) {
        unpack2(acc2[k], lo, hi);
        act[(2 * k + 0) * BLOCK + tid] = softplus10(lo);
        act[(2 * k + 1) * BLOCK + tid] = softplus10(hi);
    }

    layer_accum<64>(wt3, act, tid, acc2);

    float sdf = 0.0f;
#pragma unroll
    for (int k = 0; k < 32; k++) {
        unpack2(acc2[k], lo, hi);
        sdf = fmaf(softplus10(lo), w4s[2 * k + 0], sdf);
        sdf = fmaf(softplus10(hi), w4s[2 * k + 1], sdf);
    }

    out[p] = sdf;
}

extern "C" void kernel_launch(void* const* d_in, const int* in_sizes, int n_in,
                              void* d_out, int out_size)
{
    const float* x    = (const float*)d_in[0];
    const float* grid = (const float*)d_in[1];
    const float* W1   = (const float*)d_in[2];
    const float* W2   = (const float*)d_in[3];
    const float* W3   = (const float*)d_in[4];
    const float* W4   = (const float*)d_in[5];
    float* out = (float*)d_out;

    const int N = in_sizes[0] / 3;

    Meta meta;
    const double Bv = pow(2.0, log2(2048.0 / 16.0) / (double)(N_LEVELS - 1));
    unsigned mask = 0;
    for (int l = 0; l < N_LEVELS; l++) {
        double sc = 16.0 * pow(Bv, (double)l) - 1.0;
        int res = (int)ceil(sc) + 1;
        meta.scale[l] = (float)sc;
        meta.res[l] = res;
        if ((long long)res * res * res > (long long)TBL) mask |= (1u << l);
    }
    meta.hashed_mask = mask;

    const size_t smem = (size_t)(32 * 64 + 64 * 64 + 64 * 64 + 64 + 64 * BLOCK) * sizeof(float);
    cudaFuncSetAttribute(sdf_kernel, cudaFuncAttributeMaxDynamicSharedMemorySize, (int)smem);

    const int blocks = (N + BLOCK - 1) / BLOCK;
    sdf_kernel<<<blocks, BLOCK, smem>>>(x, grid, W1, W2, W3, W4, out, N, meta);
}

// round 3
// speedup vs baseline: 1.2940x; 1.2940x over previous
#include <cuda_runtime.h>
#include <cuda_bf16.h>
#include <math.h>

#define N_LEVELS 16
#define TBL (1u << 19)
#define BLOCK 128   // threads per block == points per block

struct Meta {
    float scale[N_LEVELS];
    int   res[N_LEVELS];
    unsigned hashed_mask;
};

__device__ __forceinline__ float softplus10(float v) {
    float t = 10.0f * v;
    float e = __expf(-fabsf(t));
    return (log1pf(e) + fmaxf(t, 0.0f)) * 0.1f;
}

__device__ __forceinline__ unsigned long long pack2(float a) {
    unsigned long long r;
    asm("mov.b64 %0, {%1, %1};" : "=l"(r) : "r"(__float_as_uint(a)));
    return r;
}

__device__ __forceinline__ void fma2(unsigned long long& acc,
                                     unsigned long long w,
                                     unsigned long long a) {
    asm("fma.rn.f32x2 %0, %1, %2, %0;" : "+l"(acc) : "l"(w), "l"(a));
}

__device__ __forceinline__ void unpack2(unsigned long long v, float& lo, float& hi) {
    unsigned ulo, uhi;
    asm("mov.b64 {%0, %1}, %2;" : "=r"(ulo), "=r"(uhi) : "l"(v));
    lo = __uint_as_float(ulo);
    hi = __uint_as_float(uhi);
}

// Each thread: 4 points (d=0..3) x 16 outputs (its j-quarter, 8 f32x2 pairs).
// acc2[d*8+k] holds outputs j = q*16 + 2k, 2k+1 for point d.
// wtq = wt + q*16 (input-major, row stride 64); actp = act + w*32 + 4*pidx.
template <int NIN>
__device__ __forceinline__ void layer_accum(const float* __restrict__ wtq,
                                            const float* __restrict__ actp,
                                            unsigned long long* acc2) {
#pragma unroll
    for (int k = 0; k < 32; k++) acc2[k] = 0ull;
#pragma unroll 4
    for (int i = 0; i < NIN; i++) {
        float4 a = *(const float4*)(actp + i * BLOCK);
        unsigned long long a2[4];
        a2[0] = pack2(a.x); a2[1] = pack2(a.y);
        a2[2] = pack2(a.z); a2[3] = pack2(a.w);
        const ulonglong2* wr = (const ulonglong2*)(wtq + i * 64);
#pragma unroll
        for (int u = 0; u < 4; u++) {
            ulonglong2 w = wr[u];
#pragma unroll
            for (int d = 0; d < 4; d++) {
                fma2(acc2[d * 8 + 2 * u + 0], w.x, a2[d]);
                fma2(acc2[d * 8 + 2 * u + 1], w.y, a2[d]);
            }
        }
    }
}

// softplus + transpose-in-thread writeback: act[j][point] rows for our quarter.
__device__ __forceinline__ void writeback_softplus(float* __restrict__ act,
                                                   const unsigned long long* acc2,
                                                   int q, int woff) {
#pragma unroll
    for (int k = 0; k < 8; k++) {
        float lo[4], hi[4];
#pragma unroll
        for (int d = 0; d < 4; d++) {
            float l, h;
            unpack2(acc2[d * 8 + k], l, h);
            lo[d] = softplus10(l);
            hi[d] = softplus10(h);
        }
        *(float4*)(act + (q * 16 + 2 * k + 0) * BLOCK + woff) =
            make_float4(lo[0], lo[1], lo[2], lo[3]);
        *(float4*)(act + (q * 16 + 2 * k + 1) * BLOCK + woff) =
            make_float4(hi[0], hi[1], hi[2], hi[3]);
    }
}

__global__ void __launch_bounds__(BLOCK)
sdf_kernel(const float* __restrict__ x,
           const float* __restrict__ grid,
           const float* __restrict__ W1,
           const float* __restrict__ W2,
           const float* __restrict__ W3,
           const float* __restrict__ W4,
           float* __restrict__ out,
           int N, Meta meta)
{
    extern __shared__ float sm[];
    float* wt1 = sm;                 // [32][64] transposed W1
    float* wt2 = wt1 + 32 * 64;      // [64][64] transposed W2
    float* wt3 = wt2 + 64 * 64;      // [64][64] transposed W3
    float* w4s = wt3 + 64 * 64;      // [64]
    float* act = w4s + 64;           // [64][BLOCK] act[j or i][point]

    const int tid = threadIdx.x;

    // Cooperative weight load with transpose (input-major rows of 64 floats)
    for (int idx = tid; idx < 64 * 32; idx += BLOCK) {
        int j = idx >> 5, i = idx & 31;          // W1[j][i]
        wt1[i * 64 + j] = W1[idx];
    }
    for (int idx = tid; idx < 64 * 64; idx += BLOCK) {
        int j = idx >> 6, i = idx & 63;
        wt2[i * 64 + j] = W2[idx];
        wt3[i * 64 + j] = W3[idx];
    }
    if (tid < 64) w4s[tid] = W4[tid];
    __syncthreads();

    // ---- Encoding: thread tid <-> point tid of this block ----
    const int p = blockIdx.x * BLOCK + tid;
    if (p < N) {
        const float px = x[p * 3 + 0];
        const float py = x[p * 3 + 1];
        const float pz = x[p * 3 + 2];

        for (int l = 0; l < N_LEVELS; l++) {
            const float s = meta.scale[l];
            const int res = meta.res[l];
            const bool hashed = (meta.hashed_mask >> l) & 1u;

            float fx = fmaf(px, s, 0.5f);
            float fy = fmaf(py, s, 0.5f);
            float fz = fmaf(pz, s, 0.5f);
            float fx0 = floorf(fx), fy0 = floorf(fy), fz0 = floorf(fz);
            float rx = fx - fx0, ry = fy - fy0, rz = fz - fz0;
            int ix = (int)fx0, iy = (int)fy0, iz = (int)fz0;

            const float2* g = (const float2*)grid + (size_t)l * TBL;
            float a0 = 0.0f, a1 = 0.0f;

#pragma unroll
            for (int c = 0; c < 8; c++) {
                const int cx = c & 1, cy = (c >> 1) & 1, cz = (c >> 2) & 1;
                float w = (cx ? rx : 1.0f - rx) *
                          (cy ? ry : 1.0f - ry) *
                          (cz ? rz : 1.0f - rz);
                unsigned idx;
                if (hashed) {
                    unsigned gx = (unsigned)(ix + cx);
                    unsigned gy = (unsigned)(iy + cy);
                    unsigned gz = (unsigned)(iz + cz);
                    idx = (gx * 1u) ^ (gy * 2654435761u) ^ (gz * 805459861u);
                    idx &= (TBL - 1u);
                } else {
                    int gx = min(max(ix + cx, 0), res - 1);
                    int gy = min(max(iy + cy, 0), res - 1);
                    int gz = min(max(iz + cz, 0), res - 1);
                    idx = (unsigned)(gx + res * (gy + res * gz));
                }
                float2 f = __ldg(&g[idx]);
                a0 = fmaf(w, f.x, a0);
                a1 = fmaf(w, f.y, a1);
            }
            act[(2 * l + 0) * BLOCK + tid] = a0;
            act[(2 * l + 1) * BLOCK + tid] = a1;
        }
    }
    __syncwarp();   // act producers/consumers are intra-warp throughout

    // ---- MLP: remap lanes to (pidx, quarter). warp covers 32 points ----
    const int w    = tid >> 5;
    const int lane = tid & 31;
    const int pidx = lane & 7;        // which group of 4 points
    const int q    = lane >> 3;       // which j-quarter (16 outputs)
    const int woff = w * 32 + 4 * pidx;  // point offset within block

    const float* actp = act + woff;
    unsigned long long acc2[32];

    layer_accum<32>(wt1 + q * 16, actp, acc2);
    writeback_softplus(act, acc2, q, woff);
    __syncwarp();

    layer_accum<64>(wt2 + q * 16, actp, acc2);
    writeback_softplus(act, acc2, q, woff);
    __syncwarp();

    layer_accum<64>(wt3 + q * 16, actp, acc2);

    // ---- Output layer: partial dot with W4 quarter, reduce across q ----
    float sdf[4] = {0.0f, 0.0f, 0.0f, 0.0f};
#pragma unroll
    for (int k = 0; k < 8; k++) {
        float w4a = w4s[q * 16 + 2 * k + 0];
        float w4b = w4s[q * 16 + 2 * k + 1];
#pragma unroll
        for (int d = 0; d < 4; d++) {
            float l, h;
            unpack2(acc2[d * 8 + k], l, h);
            sdf[d] = fmaf(softplus10(l), w4a, sdf[d]);
            sdf[d] = fmaf(softplus10(h), w4b, sdf[d]);
        }
    }
#pragma unroll
    for (int d = 0; d < 4; d++) {
        sdf[d] += __shfl_xor_sync(0xffffffffu, sdf[d], 8);
        sdf[d] += __shfl_xor_sync(0xffffffffu, sdf[d], 16);
    }
    if (q == 0) {
        const int pbase = blockIdx.x * BLOCK + woff;
#pragma unroll
        for (int d = 0; d < 4; d++) {
            if (pbase + d < N) out[pbase + d] = sdf[d];
        }
    }
}

extern "C" void kernel_launch(void* const* d_in, const int* in_sizes, int n_in,
                              void* d_out, int out_size)
{
    const float* x    = (const float*)d_in[0];
    const float* grid = (const float*)d_in[1];
    const float* W1   = (const float*)d_in[2];
    const float* W2   = (const float*)d_in[3];
    const float* W3   = (const float*)d_in[4];
    const float* W4   = (const float*)d_in[5];
    float* out = (float*)d_out;

    const int N = in_sizes[0] / 3;

    Meta meta;
    const double Bv = pow(2.0, log2(2048.0 / 16.0) / (double)(N_LEVELS - 1));
    unsigned mask = 0;
    for (int l = 0; l < N_LEVELS; l++) {
        double sc = 16.0 * pow(Bv, (double)l) - 1.0;
        int res = (int)ceil(sc) + 1;
        meta.scale[l] = (float)sc;
        meta.res[l] = res;
        if ((long long)res * res * res > (long long)TBL) mask |= (1u << l);
    }
    meta.hashed_mask = mask;

    const size_t smem = (size_t)(32 * 64 + 64 * 64 + 64 * 64 + 64 + 64 * BLOCK) * sizeof(float);
    cudaFuncSetAttribute(sdf_kernel, cudaFuncAttributeMaxDynamicSharedMemorySize, (int)smem);

    const int blocks = (N + BLOCK - 1) / BLOCK;
    sdf_kernel<<<blocks, BLOCK, smem>>>(x, grid, W1, W2, W3, W4, out, N, meta);
}

// round 4
// speedup vs baseline: 1.5440x; 1.1932x over previous
#include <cuda_runtime.h>
#include <cuda_bf16.h>
#include <math.h>

#define N_LEVELS 16
#define TBL (1u << 19)
#define BLOCK 128   // threads per block == points per block

struct Meta {
    float scale[N_LEVELS];
    int   res[N_LEVELS];
    unsigned hashed_mask;
};

// Transposed weights live in global scratch (L1-hot), not per-CTA smem.
// Layout: [ wt1t: 32*64 | wt2t: 64*64 | wt3t: 64*64 | w4: 64 ]  (input-major rows of 64)
__device__ float g_wt[32 * 64 + 64 * 64 + 64 * 64 + 64];

__device__ __forceinline__ float softplus10(float v) {
    float t = 10.0f * v;
    float e = __expf(-fabsf(t));
    return (log1pf(e) + fmaxf(t, 0.0f)) * 0.1f;
}

__device__ __forceinline__ unsigned long long pack2(float a) {
    unsigned long long r;
    asm("mov.b64 %0, {%1, %1};" : "=l"(r) : "r"(__float_as_uint(a)));
    return r;
}

__device__ __forceinline__ void fma2(unsigned long long& acc,
                                     unsigned long long w,
                                     unsigned long long a) {
    asm("fma.rn.f32x2 %0, %1, %2, %0;" : "+l"(acc) : "l"(w), "l"(a));
}

__device__ __forceinline__ void unpack2(unsigned long long v, float& lo, float& hi) {
    unsigned ulo, uhi;
    asm("mov.b64 {%0, %1}, %2;" : "=r"(ulo), "=r"(uhi) : "l"(v));
    lo = __uint_as_float(ulo);
    hi = __uint_as_float(uhi);
}

__global__ void prep_weights(const float* __restrict__ W1,
                             const float* __restrict__ W2,
                             const float* __restrict__ W3,
                             const float* __restrict__ W4)
{
    const int tid = blockIdx.x * blockDim.x + threadIdx.x;
    // W1 [64][32] -> wt1t[i*64 + j]
    for (int idx = tid; idx < 64 * 32; idx += gridDim.x * blockDim.x) {
        int j = idx >> 5, i = idx & 31;
        g_wt[i * 64 + j] = W1[idx];
    }
    for (int idx = tid; idx < 64 * 64; idx += gridDim.x * blockDim.x) {
        int j = idx >> 6, i = idx & 63;
        g_wt[32 * 64 + i * 64 + j] = W2[idx];
        g_wt[32 * 64 + 64 * 64 + i * 64 + j] = W3[idx];
    }
    if (tid < 64) g_wt[32 * 64 + 2 * 64 * 64 + tid] = W4[tid];
}

// Each thread: 4 points (d=0..3) x 16 outputs (its j-quarter, 8 f32x2 pairs).
// wtq = wt + q*16 (input-major, row stride 64, GLOBAL, L1-hot); actp smem.
template <int NIN>
__device__ __forceinline__ void layer_accum(const float* __restrict__ wtq,
                                            const float* __restrict__ actp,
                                            unsigned long long* acc2) {
#pragma unroll
    for (int k = 0; k < 32; k++) acc2[k] = 0ull;
#pragma unroll 4
    for (int i = 0; i < NIN; i++) {
        float4 a = *(const float4*)(actp + i * BLOCK);
        unsigned long long a2[4];
        a2[0] = pack2(a.x); a2[1] = pack2(a.y);
        a2[2] = pack2(a.z); a2[3] = pack2(a.w);
        const ulonglong2* wr = (const ulonglong2*)(wtq + i * 64);
#pragma unroll
        for (int u = 0; u < 4; u++) {
            ulonglong2 w = __ldg(&wr[u]);
#pragma unroll
            for (int d = 0; d < 4; d++) {
                fma2(acc2[d * 8 + 2 * u + 0], w.x, a2[d]);
                fma2(acc2[d * 8 + 2 * u + 1], w.y, a2[d]);
            }
        }
    }
}

__device__ __forceinline__ void writeback_softplus(float* __restrict__ act,
                                                   const unsigned long long* acc2,
                                                   int q, int woff) {
#pragma unroll
    for (int k = 0; k < 8; k++) {
        float lo[4], hi[4];
#pragma unroll
        for (int d = 0; d < 4; d++) {
            float l, h;
            unpack2(acc2[d * 8 + k], l, h);
            lo[d] = softplus10(l);
            hi[d] = softplus10(h);
        }
        *(float4*)(act + (q * 16 + 2 * k + 0) * BLOCK + woff) =
            make_float4(lo[0], lo[1], lo[2], lo[3]);
        *(float4*)(act + (q * 16 + 2 * k + 1) * BLOCK + woff) =
            make_float4(hi[0], hi[1], hi[2], hi[3]);
    }
}

__global__ void __launch_bounds__(BLOCK)
sdf_kernel(const float* __restrict__ x,
           const float* __restrict__ grid,
           float* __restrict__ out,
           int N, Meta meta)
{
    // smem: ONLY activations -> 32 KB -> 7 CTAs/SM
    extern __shared__ float act[];   // [64][BLOCK]

    const int tid = threadIdx.x;

    // ---- Encoding: thread tid <-> point tid of this block ----
    const int p = blockIdx.x * BLOCK + tid;
    if (p < N) {
        const float px = x[p * 3 + 0];
        const float py = x[p * 3 + 1];
        const float pz = x[p * 3 + 2];

        for (int l = 0; l < N_LEVELS; l++) {
            const float s = meta.scale[l];
            const int res = meta.res[l];
            const bool hashed = (meta.hashed_mask >> l) & 1u;

            float fx = fmaf(px, s, 0.5f);
            float fy = fmaf(py, s, 0.5f);
            float fz = fmaf(pz, s, 0.5f);
            float fx0 = floorf(fx), fy0 = floorf(fy), fz0 = floorf(fz);
            float rx = fx - fx0, ry = fy - fy0, rz = fz - fz0;
            int ix = (int)fx0, iy = (int)fy0, iz = (int)fz0;

            const float2* g = (const float2*)grid + (size_t)l * TBL;
            float a0 = 0.0f, a1 = 0.0f;

#pragma unroll
            for (int c = 0; c < 8; c++) {
                const int cx = c & 1, cy = (c >> 1) & 1, cz = (c >> 2) & 1;
                float w = (cx ? rx : 1.0f - rx) *
                          (cy ? ry : 1.0f - ry) *
                          (cz ? rz : 1.0f - rz);
                unsigned idx;
                if (hashed) {
                    unsigned gx = (unsigned)(ix + cx);
                    unsigned gy = (unsigned)(iy + cy);
                    unsigned gz = (unsigned)(iz + cz);
                    idx = (gx * 1u) ^ (gy * 2654435761u) ^ (gz * 805459861u);
                    idx &= (TBL - 1u);
                } else {
                    int gx = min(max(ix + cx, 0), res - 1);
                    int gy = min(max(iy + cy, 0), res - 1);
                    int gz = min(max(iz + cz, 0), res - 1);
                    idx = (unsigned)(gx + res * (gy + res * gz));
                }
                float2 f = __ldg(&g[idx]);
                a0 = fmaf(w, f.x, a0);
                a1 = fmaf(w, f.y, a1);
            }
            act[(2 * l + 0) * BLOCK + tid] = a0;
            act[(2 * l + 1) * BLOCK + tid] = a1;
        }
    }
    __syncwarp();   // act producers/consumers are intra-warp throughout

    // ---- MLP: lanes -> (pidx, quarter). warp covers 32 points ----
    const int w    = tid >> 5;
    const int lane = tid & 31;
    const int pidx = lane & 7;        // which group of 4 points
    const int q    = lane >> 3;       // which j-quarter (16 outputs)
    const int woff = w * 32 + 4 * pidx;

    const float* actp = act + woff;
    const float* wt1 = g_wt;
    const float* wt2 = g_wt + 32 * 64;
    const float* wt3 = g_wt + 32 * 64 + 64 * 64;
    const float* w4g = g_wt + 32 * 64 + 2 * 64 * 64;

    unsigned long long acc2[32];

    layer_accum<32>(wt1 + q * 16, actp, acc2);
    writeback_softplus(act, acc2, q, woff);
    __syncwarp();

    layer_accum<64>(wt2 + q * 16, actp, acc2);
    writeback_softplus(act, acc2, q, woff);
    __syncwarp();

    layer_accum<64>(wt3 + q * 16, actp, acc2);

    // ---- Output layer: partial dot with W4 quarter, reduce across q ----
    float sdf[4] = {0.0f, 0.0f, 0.0f, 0.0f};
#pragma unroll
    for (int k = 0; k < 8; k++) {
        float w4a = __ldg(&w4g[q * 16 + 2 * k + 0]);
        float w4b = __ldg(&w4g[q * 16 + 2 * k + 1]);
#pragma unroll
        for (int d = 0; d < 4; d++) {
            float l, h;
            unpack2(acc2[d * 8 + k], l, h);
            sdf[d] = fmaf(softplus10(l), w4a, sdf[d]);
            sdf[d] = fmaf(softplus10(h), w4b, sdf[d]);
        }
    }
#pragma unroll
    for (int d = 0; d < 4; d++) {
        sdf[d] += __shfl_xor_sync(0xffffffffu, sdf[d], 8);
        sdf[d] += __shfl_xor_sync(0xffffffffu, sdf[d], 16);
    }
    if (q == 0) {
        const int pbase = blockIdx.x * BLOCK + woff;
#pragma unroll
        for (int d = 0; d < 4; d++) {
            if (pbase + d < N) out[pbase + d] = sdf[d];
        }
    }
}

extern "C" void kernel_launch(void* const* d_in, const int* in_sizes, int n_in,
                              void* d_out, int out_size)
{
    const float* x    = (const float*)d_in[0];
    const float* grid = (const float*)d_in[1];
    const float* W1   = (const float*)d_in[2];
    const float* W2   = (const float*)d_in[3];
    const float* W3   = (const float*)d_in[4];
    const float* W4   = (const float*)d_in[5];
    float* out = (float*)d_out;

    const int N = in_sizes[0] / 3;

    Meta meta;
    const double Bv = pow(2.0, log2(2048.0 / 16.0) / (double)(N_LEVELS - 1));
    unsigned mask = 0;
    for (int l = 0; l < N_LEVELS; l++) {
        double sc = 16.0 * pow(Bv, (double)l) - 1.0;
        int res = (int)ceil(sc) + 1;
        meta.scale[l] = (float)sc;
        meta.res[l] = res;
        if ((long long)res * res * res > (long long)TBL) mask |= (1u << l);
    }
    meta.hashed_mask = mask;

    prep_weights<<<16, 256>>>(W1, W2, W3, W4);

    const size_t smem = (size_t)(64 * BLOCK) * sizeof(float);   // exactly 32 KB
    const int blocks = (N + BLOCK - 1) / BLOCK;
    sdf_kernel<<<blocks, BLOCK, smem>>>(x, grid, out, N, meta);
}